// round 1
// baseline (speedup 1.0000x reference)
#include <cuda_runtime.h>
#include <math.h>

#define Bn 2
#define Tt 4
#define NC 3
#define NK 16
#define Hh 180
#define Ww 320
#define HW (Hh*Ww)
#define KK 3
#define K2 9
#define CIN_D (Tt*NK)   // 64
#define OUT_C 48        // NC*SCALE^2
#define SCALE 4

// Scratch (no cudaMalloc allowed)
__device__ float g_hs[Bn*CIN_D*HW];    // ConvLSTM hidden states, laid out as [B, t*16+k, H, W]
__device__ float g_c[Bn*NK*HW];        // cell state
__device__ float g_om[Bn*27*HW];       // 18 offsets + 9 masks (mask pre-activated: 2*sigmoid)
__device__ float g_def[Bn*NK*HW];      // deformable conv output

__device__ __forceinline__ float sigmoidf_(float v) {
    return 1.f / (1.f + __expf(-v));
}

// ---------------------------------------------------------------------------
// ConvLSTM step: conv(concat(x_t, h_{t-1}); 19->64) + gates, fused.
// block = (32,8) spatial tile, blockIdx.z = b*16 + k
// ---------------------------------------------------------------------------
__global__ void lstm_step_kernel(const float* __restrict__ X,
                                 const float* __restrict__ lw,
                                 const float* __restrict__ lb,
                                 const float* __restrict__ Wci,
                                 const float* __restrict__ Wcf,
                                 const float* __restrict__ Wco,
                                 int t)
{
    const int bx = blockIdx.x * 32, by = blockIdx.y * 8;
    const int bz = blockIdx.z;
    const int b = bz >> 4, k = bz & 15;
    const int tx = threadIdx.x, ty = threadIdx.y;
    const int tid = ty * 32 + tx;

    __shared__ float sw[4 * 19 * 9];   // weights for 4 gates of channel k
    __shared__ float sp[10][34];       // input patch (one channel at a time)

    for (int i = tid; i < 4 * 171; i += 256) {
        int gate = i / 171, rest = i - gate * 171;
        sw[i] = lw[(gate * NK + k) * 171 + rest];
    }

    const int x = bx + tx, y = by + ty;
    float a0 = lb[k], a1 = lb[NK + k], a2 = lb[2 * NK + k], a3 = lb[3 * NK + k];
    const int ncin = (t == 0) ? NC : (NC + NK);

    for (int ci = 0; ci < ncin; ci++) {
        const float* src = (ci < NC)
            ? (X + (((size_t)b * Tt + t) * NC + ci) * HW)
            : (g_hs + ((size_t)b * CIN_D + (t - 1) * NK + (ci - NC)) * HW);
        __syncthreads();
        for (int i = tid; i < 340; i += 256) {
            int pr = i / 34, pc = i - pr * 34;
            int gy = by - 1 + pr, gx = bx - 1 + pc;
            float v = 0.f;
            if (gy >= 0 && gy < Hh && gx >= 0 && gx < Ww) v = src[gy * Ww + gx];
            sp[pr][pc] = v;
        }
        __syncthreads();
        const float* w0 = sw + ci * 9;
        #pragma unroll
        for (int dy = 0; dy < 3; dy++)
            #pragma unroll
            for (int dx = 0; dx < 3; dx++) {
                float v = sp[ty + dy][tx + dx];
                int wi = dy * 3 + dx;
                a0 += v * w0[wi];
                a1 += v * w0[171 + wi];
                a2 += v * w0[342 + wi];
                a3 += v * w0[513 + wi];
            }
    }

    if (y < Hh) {
        int idxk = k * HW + y * Ww + x;
        float cprev = (t == 0) ? 0.f : g_c[b * NK * HW + idxk];
        float ig = sigmoidf_(a0 + Wci[idxk] * cprev);
        float fg = sigmoidf_(a1 + Wcf[idxk] * cprev);
        float cn = fg * cprev + ig * tanhf(a2);
        float og = sigmoidf_(a3 + Wco[idxk] * cn);
        g_c[b * NK * HW + idxk] = cn;
        g_hs[((size_t)b * CIN_D + t * NK + k) * HW + y * Ww + x] = og * tanhf(cn);
    }
}

// ---------------------------------------------------------------------------
// Offset (18 ch, raw) + modulation (9 ch, 2*sigmoid fused) conv: 64 -> 27
// blockIdx.z = b*27 + oc
// ---------------------------------------------------------------------------
__global__ void offmask_kernel(const float* __restrict__ off_w,
                               const float* __restrict__ off_b,
                               const float* __restrict__ mod_w,
                               const float* __restrict__ mod_b)
{
    const int bx = blockIdx.x * 32, by = blockIdx.y * 8;
    const int bz = blockIdx.z;
    const int b = bz / 27, oc = bz - b * 27;
    const int tx = threadIdx.x, ty = threadIdx.y;
    const int tid = ty * 32 + tx;

    __shared__ float sw[64 * 9];
    __shared__ float sp[10][34];

    const bool is_mask = (oc >= 18);
    const float* wsrc = is_mask ? (mod_w + (size_t)(oc - 18) * 576) : (off_w + (size_t)oc * 576);
    float bias = is_mask ? mod_b[oc - 18] : off_b[oc];

    for (int i = tid; i < 576; i += 256) sw[i] = wsrc[i];

    const int x = bx + tx, y = by + ty;
    float acc = bias;

    for (int ci = 0; ci < CIN_D; ci++) {
        const float* src = g_hs + ((size_t)b * CIN_D + ci) * HW;
        __syncthreads();
        for (int i = tid; i < 340; i += 256) {
            int pr = i / 34, pc = i - pr * 34;
            int gy = by - 1 + pr, gx = bx - 1 + pc;
            float v = 0.f;
            if (gy >= 0 && gy < Hh && gx >= 0 && gx < Ww) v = src[gy * Ww + gx];
            sp[pr][pc] = v;
        }
        __syncthreads();
        const float* w0 = sw + ci * 9;
        #pragma unroll
        for (int dy = 0; dy < 3; dy++)
            #pragma unroll
            for (int dx = 0; dx < 3; dx++)
                acc += sp[ty + dy][tx + dx] * w0[dy * 3 + dx];
    }

    if (y < Hh) {
        if (is_mask) acc = 2.f * sigmoidf_(acc);
        g_om[((size_t)b * 27 + oc) * HW + y * Ww + x] = acc;
    }
}

// ---------------------------------------------------------------------------
// Modulated deformable conv: bilinear gather over 64 ch x 9 points + einsum -> 16 ch
// blockIdx.z = b; one thread per pixel computes all 16 outputs.
// ---------------------------------------------------------------------------
__global__ void deform_kernel(const float* __restrict__ def_w,
                              const float* __restrict__ def_b)
{
    const int bx = blockIdx.x * 32, by = blockIdx.y * 8;
    const int b = blockIdx.z;
    const int tx = threadIdx.x, ty = threadIdx.y;
    const int tid = ty * 32 + tx;

    __shared__ float sw[NK * CIN_D * 9];   // 9216 floats = 36 KB
    __shared__ float sb[NK];

    for (int i = tid; i < NK * CIN_D * 9; i += 256) sw[i] = def_w[i];
    if (tid < NK) sb[tid] = def_b[tid];
    __syncthreads();

    const int x = bx + tx, y = by + ty;
    if (y >= Hh) return;
    const int p = y * Ww + x;

    const float* xb = g_hs + (size_t)b * CIN_D * HW;
    const float* om = g_om + (size_t)b * 27 * HW;

    float acc[NK];
    #pragma unroll
    for (int o = 0; o < NK; o++) acc[o] = sb[o];

    for (int j = 0; j < 9; j++) {
        int ky = j / 3, kx = j - ky * 3;
        float dy = om[(2 * j) * HW + p];
        float dx = om[(2 * j + 1) * HW + p];
        float m  = om[(18 + j) * HW + p];
        float py = (float)(y - 1 + ky) + dy;
        float px = (float)(x - 1 + kx) + dx;
        float y0f = floorf(py), x0f = floorf(px);
        float wy = py - y0f, wx = px - x0f;
        int y0 = (int)y0f, x0 = (int)x0f;
        int y1 = y0 + 1,   x1 = x0 + 1;
        float vy0 = (y0 >= 0 && y0 < Hh) ? 1.f : 0.f;
        float vy1 = (y1 >= 0 && y1 < Hh) ? 1.f : 0.f;
        float vx0 = (x0 >= 0 && x0 < Ww) ? 1.f : 0.f;
        float vx1 = (x1 >= 0 && x1 < Ww) ? 1.f : 0.f;
        int y0c = min(max(y0, 0), Hh - 1), y1c = min(max(y1, 0), Hh - 1);
        int x0c = min(max(x0, 0), Ww - 1), x1c = min(max(x1, 0), Ww - 1);
        float w00 = (1.f - wy) * (1.f - wx) * vy0 * vx0 * m;
        float w01 = (1.f - wy) * wx         * vy0 * vx1 * m;
        float w10 = wy * (1.f - wx)         * vy1 * vx0 * m;
        float w11 = wy * wx                 * vy1 * vx1 * m;
        int o00 = y0c * Ww + x0c, o01 = y0c * Ww + x1c;
        int o10 = y1c * Ww + x0c, o11 = y1c * Ww + x1c;

        for (int c = 0; c < CIN_D; c++) {
            const float* pc_ = xb + (size_t)c * HW;
            float s = w00 * pc_[o00] + w01 * pc_[o01]
                    + w10 * pc_[o10] + w11 * pc_[o11];
            const float* wrow = sw + c * 9 + j;
            #pragma unroll
            for (int o = 0; o < NK; o++)
                acc[o] += s * wrow[o * CIN_D * 9];
        }
    }

    #pragma unroll
    for (int o = 0; o < NK; o++)
        g_def[((size_t)b * NK + o) * HW + p] = acc[o];
}

// ---------------------------------------------------------------------------
// Output conv 16 -> 48, fused pixel shuffle (r=4) + clip to d_out [2,3,720,1280]
// blockIdx.z = b
// ---------------------------------------------------------------------------
__global__ void outconv_kernel(const float* __restrict__ out_w,
                               const float* __restrict__ out_b,
                               float* __restrict__ out)
{
    const int bx = blockIdx.x * 32, by = blockIdx.y * 8;
    const int b = blockIdx.z;
    const int tx = threadIdx.x, ty = threadIdx.y;
    const int tid = ty * 32 + tx;

    __shared__ float sw[OUT_C * NK * 9];  // 6912 floats = 27.6 KB
    __shared__ float sp[10][34];

    for (int i = tid; i < OUT_C * NK * 9; i += 256) sw[i] = out_w[i];

    const int x = bx + tx, y = by + ty;
    float acc[OUT_C];
    #pragma unroll
    for (int oc = 0; oc < OUT_C; oc++) acc[oc] = out_b[oc];

    for (int ci = 0; ci < NK; ci++) {
        const float* src = g_def + ((size_t)b * NK + ci) * HW;
        __syncthreads();
        for (int i = tid; i < 340; i += 256) {
            int pr = i / 34, pc = i - pr * 34;
            int gy = by - 1 + pr, gx = bx - 1 + pc;
            float v = 0.f;
            if (gy >= 0 && gy < Hh && gx >= 0 && gx < Ww) v = src[gy * Ww + gx];
            sp[pr][pc] = v;
        }
        __syncthreads();
        float v[9];
        #pragma unroll
        for (int dy = 0; dy < 3; dy++)
            #pragma unroll
            for (int dx = 0; dx < 3; dx++)
                v[dy * 3 + dx] = sp[ty + dy][tx + dx];
        const float* w0 = sw + ci * 9;
        #pragma unroll
        for (int oc = 0; oc < OUT_C; oc++) {
            const float* wr = w0 + oc * NK * 9;
            #pragma unroll
            for (int t9 = 0; t9 < 9; t9++)
                acc[oc] += v[t9] * wr[t9];
        }
    }

    if (y < Hh) {
        #pragma unroll
        for (int oc = 0; oc < OUT_C; oc++) {
            int cch = oc >> 4;
            int rem = oc & 15;
            int r1 = rem >> 2, r2 = rem & 3;
            float val = fminf(fmaxf(acc[oc], 0.f), 255.f);
            size_t oi = (((size_t)b * NC + cch) * (Hh * SCALE) + (y * SCALE + r1))
                        * (size_t)(Ww * SCALE) + (x * SCALE + r2);
            out[oi] = val;
        }
    }
}

// ---------------------------------------------------------------------------
extern "C" void kernel_launch(void* const* d_in, const int* in_sizes, int n_in,
                              void* d_out, int out_size)
{
    const float* X      = (const float*)d_in[0];
    const float* lstm_w = (const float*)d_in[1];
    const float* lstm_b = (const float*)d_in[2];
    const float* W_ci   = (const float*)d_in[3];
    const float* W_cf   = (const float*)d_in[4];
    const float* W_co   = (const float*)d_in[5];
    const float* off_w  = (const float*)d_in[6];
    const float* off_b  = (const float*)d_in[7];
    const float* mod_w  = (const float*)d_in[8];
    const float* mod_b  = (const float*)d_in[9];
    const float* def_w  = (const float*)d_in[10];
    const float* def_b  = (const float*)d_in[11];
    const float* out_w  = (const float*)d_in[12];
    const float* out_b  = (const float*)d_in[13];
    float* out = (float*)d_out;

    dim3 blk(32, 8);
    dim3 grid_lstm(Ww / 32, (Hh + 7) / 8, Bn * NK);
    dim3 grid_om(Ww / 32, (Hh + 7) / 8, Bn * 27);
    dim3 grid_b(Ww / 32, (Hh + 7) / 8, Bn);

    for (int t = 0; t < Tt; t++)
        lstm_step_kernel<<<grid_lstm, blk>>>(X, lstm_w, lstm_b, W_ci, W_cf, W_co, t);

    offmask_kernel<<<grid_om, blk>>>(off_w, off_b, mod_w, mod_b);
    deform_kernel<<<grid_b, blk>>>(def_w, def_b);
    outconv_kernel<<<grid_b, blk>>>(out_w, out_b, out);
}

// round 2
// speedup vs baseline: 1.8629x; 1.8629x over previous
#include <cuda_runtime.h>
#include <math.h>

#define Bn 2
#define Tt 4
#define NC 3
#define NK 16
#define Hh 180
#define Ww 320
#define HW (Hh*Ww)
#define K2 9
#define CIN_D (Tt*NK)   // 64
#define OUT_C 48
#define SCALE 4

#define LTW 64          // tile width (pixels)
#define LTH 16          // tile height
#define SPW 66          // staged patch width (LTW+2)
#define SPH 18          // staged patch height (LTH+2)

// Scratch (no cudaMalloc allowed)
__device__ float g_hs[Bn*CIN_D*HW];    // hidden states [b][t*16+k][H][W]
__device__ float g_c[Bn*NK*HW];        // cell state
__device__ float g_om[Bn*27*HW];       // 18 offsets + 9 masks (2*sigmoid applied)
__device__ float g_def[Bn*NK*HW];      // deformable conv output

__device__ __forceinline__ float sig_(float v) {
    return __fdividef(1.f, 1.f + __expf(-v));
}
__device__ __forceinline__ float tanh_(float v) {
    float e = __expf(2.f * v);
    return 1.f - __fdividef(2.f, e + 1.f);
}

// ---------------------------------------------------------------------------
// ConvLSTM step. block (16,16); thread = 4 adjacent px, 16 outputs (4 k x 4 gates)
// blockIdx.z = b*4 + kg  (kg selects k group of 4)
// ---------------------------------------------------------------------------
__global__ __launch_bounds__(256, 2)
void lstm_step_kernel(const float* __restrict__ X,
                      const float* __restrict__ lw,
                      const float* __restrict__ lb,
                      const float* __restrict__ Wci,
                      const float* __restrict__ Wcf,
                      const float* __restrict__ Wco,
                      int t)
{
    __shared__ float sw[19 * 9 * 16];   // [c*9+tap][16]
    __shared__ float sp[SPH * SPW];
    __shared__ float sb[16];

    const int tx = threadIdx.x, ty = threadIdx.y;
    const int tid = ty * 16 + tx;
    const int bz = blockIdx.z;
    const int b = bz >> 2, kg = bz & 3;
    const int bx = blockIdx.x * LTW, by = blockIdx.y * LTH;
    const int x0 = bx + tx * 4, y = by + ty;

    // stage weights transposed: lo = gate*4 + kk -> global row gate*16 + kg*4 + kk
    for (int i = tid; i < 19 * 9 * 16; i += 256) {
        int lo = i / 171, rest = i - lo * 171;
        int row = (lo >> 2) * NK + kg * 4 + (lo & 3);
        sw[rest * 16 + lo] = lw[row * 171 + rest];
    }
    if (tid < 16)
        sb[tid] = lb[(tid >> 2) * NK + kg * 4 + (tid & 3)];
    __syncthreads();

    float acc[16][4];
    #pragma unroll
    for (int lo = 0; lo < 16; lo++) {
        float bv = sb[lo];
        #pragma unroll
        for (int px = 0; px < 4; px++) acc[lo][px] = bv;
    }

    const int ncin = (t == 0) ? NC : (NC + NK);
    for (int c = 0; c < ncin; c++) {
        const float* src = (c < NC)
            ? (X + (((size_t)b * Tt + t) * NC + c) * HW)
            : (g_hs + ((size_t)b * CIN_D + (t - 1) * NK + (c - NC)) * HW);
        for (int i = tid; i < SPH * SPW; i += 256) {
            int pr = i / SPW, pc = i - pr * SPW;
            int gy = by - 1 + pr, gx = bx - 1 + pc;
            sp[i] = (gy >= 0 && gy < Hh && gx >= 0 && gx < Ww) ? src[gy * Ww + gx] : 0.f;
        }
        __syncthreads();
        const float* wc = sw + c * 144;
        #pragma unroll
        for (int tr = 0; tr < 3; tr++) {
            float v[6];
            const float* rowp = sp + (ty + tr) * SPW + tx * 4;
            #pragma unroll
            for (int j = 0; j < 6; j++) v[j] = rowp[j];
            #pragma unroll
            for (int tc = 0; tc < 3; tc++) {
                const float4* w4 = (const float4*)(wc + (tr * 3 + tc) * 16);
                #pragma unroll
                for (int q = 0; q < 4; q++) {
                    float4 w = w4[q];
                    #pragma unroll
                    for (int px = 0; px < 4; px++) {
                        float pv = v[tc + px];
                        acc[q * 4 + 0][px] += pv * w.x;
                        acc[q * 4 + 1][px] += pv * w.y;
                        acc[q * 4 + 2][px] += pv * w.z;
                        acc[q * 4 + 3][px] += pv * w.w;
                    }
                }
            }
        }
        __syncthreads();
    }

    if (y < Hh) {
        const int p = y * Ww + x0;
        #pragma unroll
        for (int kk = 0; kk < 4; kk++) {
            int k = kg * 4 + kk;
            float ci4[4], cf4[4], co4[4], cp4[4], cn4[4], h4[4];
            *(float4*)ci4 = *(const float4*)(Wci + k * HW + p);
            *(float4*)cf4 = *(const float4*)(Wcf + k * HW + p);
            *(float4*)co4 = *(const float4*)(Wco + k * HW + p);
            if (t == 0) {
                #pragma unroll
                for (int px = 0; px < 4; px++) cp4[px] = 0.f;
            } else {
                *(float4*)cp4 = *(const float4*)(g_c + ((size_t)b * NK + k) * HW + p);
            }
            #pragma unroll
            for (int px = 0; px < 4; px++) {
                float cprev = cp4[px];
                float i_ = sig_(acc[kk][px]      + ci4[px] * cprev);
                float f_ = sig_(acc[4 + kk][px]  + cf4[px] * cprev);
                float cn = f_ * cprev + i_ * tanh_(acc[8 + kk][px]);
                float o_ = sig_(acc[12 + kk][px] + co4[px] * cn);
                cn4[px] = cn;
                h4[px] = o_ * tanh_(cn);
            }
            *(float4*)(g_c + ((size_t)b * NK + k) * HW + p) = *(float4*)cn4;
            *(float4*)(g_hs + ((size_t)b * CIN_D + t * NK + k) * HW + p) = *(float4*)h4;
        }
    }
}

// ---------------------------------------------------------------------------
// Offset+mask conv 64 -> 27 (padded to 2 groups of 16). blockIdx.z = b*2 + half
// ---------------------------------------------------------------------------
__global__ __launch_bounds__(256, 2)
void offmask_kernel(const float* __restrict__ off_w,
                    const float* __restrict__ off_b,
                    const float* __restrict__ mod_w,
                    const float* __restrict__ mod_b)
{
    __shared__ float sw[16 * 576];     // [c*9+tap][16]
    __shared__ float sp[SPH * SPW];
    __shared__ float sb[16];

    const int tx = threadIdx.x, ty = threadIdx.y;
    const int tid = ty * 16 + tx;
    const int bz = blockIdx.z;
    const int b = bz >> 1, half = bz & 1;
    const int base = half * 16;
    const int count = half ? 11 : 16;
    const int bx = blockIdx.x * LTW, by = blockIdx.y * LTH;
    const int x0 = bx + tx * 4, y = by + ty;

    for (int i = tid; i < 16 * 576; i += 256) {
        int lo = i / 576, rest = i - lo * 576;
        int oc = base + lo;
        float v = 0.f;
        if (oc < 18) v = off_w[(size_t)oc * 576 + rest];
        else if (oc < 27) v = mod_w[(size_t)(oc - 18) * 576 + rest];
        sw[rest * 16 + lo] = v;
    }
    if (tid < 16) {
        int oc = base + tid;
        sb[tid] = (oc < 18) ? off_b[oc] : (oc < 27 ? mod_b[oc - 18] : 0.f);
    }
    __syncthreads();

    float acc[16][4];
    #pragma unroll
    for (int lo = 0; lo < 16; lo++) {
        float bv = sb[lo];
        #pragma unroll
        for (int px = 0; px < 4; px++) acc[lo][px] = bv;
    }

    for (int c = 0; c < CIN_D; c++) {
        const float* src = g_hs + ((size_t)b * CIN_D + c) * HW;
        for (int i = tid; i < SPH * SPW; i += 256) {
            int pr = i / SPW, pc = i - pr * SPW;
            int gy = by - 1 + pr, gx = bx - 1 + pc;
            sp[i] = (gy >= 0 && gy < Hh && gx >= 0 && gx < Ww) ? src[gy * Ww + gx] : 0.f;
        }
        __syncthreads();
        const float* wc = sw + c * 144;
        #pragma unroll
        for (int tr = 0; tr < 3; tr++) {
            float v[6];
            const float* rowp = sp + (ty + tr) * SPW + tx * 4;
            #pragma unroll
            for (int j = 0; j < 6; j++) v[j] = rowp[j];
            #pragma unroll
            for (int tc = 0; tc < 3; tc++) {
                const float4* w4 = (const float4*)(wc + (tr * 3 + tc) * 16);
                #pragma unroll
                for (int q = 0; q < 4; q++) {
                    float4 w = w4[q];
                    #pragma unroll
                    for (int px = 0; px < 4; px++) {
                        float pv = v[tc + px];
                        acc[q * 4 + 0][px] += pv * w.x;
                        acc[q * 4 + 1][px] += pv * w.y;
                        acc[q * 4 + 2][px] += pv * w.z;
                        acc[q * 4 + 3][px] += pv * w.w;
                    }
                }
            }
        }
        __syncthreads();
    }

    if (y < Hh) {
        const int p = y * Ww + x0;
        #pragma unroll
        for (int lo = 0; lo < 16; lo++) {
            if (lo >= count) break;
            int oc = base + lo;
            float o4[4];
            if (oc >= 18) {
                #pragma unroll
                for (int px = 0; px < 4; px++) o4[px] = 2.f * sig_(acc[lo][px]);
            } else {
                #pragma unroll
                for (int px = 0; px < 4; px++) o4[px] = acc[lo][px];
            }
            *(float4*)(g_om + ((size_t)b * 27 + oc) * HW + p) = *(float4*)o4;
        }
    }
}

// ---------------------------------------------------------------------------
// Modulated deformable conv. block (32,8), 1 px/thread, 16 outputs.
// ---------------------------------------------------------------------------
__global__ __launch_bounds__(256)
void deform_kernel(const float* __restrict__ def_w,
                   const float* __restrict__ def_b)
{
    __shared__ float swd[NK * CIN_D * 9];   // [c*9+j][16]
    __shared__ float sb[NK];

    const int bx = blockIdx.x * 32, by = blockIdx.y * 8;
    const int b = blockIdx.z;
    const int tx = threadIdx.x, ty = threadIdx.y;
    const int tid = ty * 32 + tx;

    for (int i = tid; i < NK * CIN_D * 9; i += 256) {
        int o = i / 576, rest = i - o * 576;
        swd[rest * 16 + o] = def_w[i];
    }
    if (tid < NK) sb[tid] = def_b[tid];
    __syncthreads();

    const int x = bx + tx, y = by + ty;
    if (y >= Hh) return;
    const int p = y * Ww + x;

    const float* xb = g_hs + (size_t)b * CIN_D * HW;
    const float* om = g_om + (size_t)b * 27 * HW;

    float acc[NK];
    #pragma unroll
    for (int o = 0; o < NK; o++) acc[o] = sb[o];

    #pragma unroll
    for (int j = 0; j < 9; j++) {
        int ky = j / 3, kx = j - ky * 3;
        float dy = om[(2 * j) * HW + p];
        float dx = om[(2 * j + 1) * HW + p];
        float m  = om[(18 + j) * HW + p];
        float py = (float)(y - 1 + ky) + dy;
        float px_ = (float)(x - 1 + kx) + dx;
        float y0f = floorf(py), x0f = floorf(px_);
        float wy = py - y0f, wx = px_ - x0f;
        int y0 = (int)y0f, x0 = (int)x0f;
        int y1 = y0 + 1,   x1 = x0 + 1;
        float vy0 = (y0 >= 0 && y0 < Hh) ? 1.f : 0.f;
        float vy1 = (y1 >= 0 && y1 < Hh) ? 1.f : 0.f;
        float vx0 = (x0 >= 0 && x0 < Ww) ? 1.f : 0.f;
        float vx1 = (x1 >= 0 && x1 < Ww) ? 1.f : 0.f;
        int y0c = min(max(y0, 0), Hh - 1), y1c = min(max(y1, 0), Hh - 1);
        int x0c = min(max(x0, 0), Ww - 1), x1c = min(max(x1, 0), Ww - 1);
        float w00 = (1.f - wy) * (1.f - wx) * vy0 * vx0 * m;
        float w01 = (1.f - wy) * wx         * vy0 * vx1 * m;
        float w10 = wy * (1.f - wx)         * vy1 * vx0 * m;
        float w11 = wy * wx                 * vy1 * vx1 * m;
        int o00 = y0c * Ww + x0c, o01 = y0c * Ww + x1c;
        int o10 = y1c * Ww + x0c, o11 = y1c * Ww + x1c;

        for (int c = 0; c < CIN_D; c++) {
            const float* pc_ = xb + (size_t)c * HW;
            float s = w00 * pc_[o00] + w01 * pc_[o01]
                    + w10 * pc_[o10] + w11 * pc_[o11];
            const float4* w4 = (const float4*)(swd + (c * 9 + j) * 16);
            #pragma unroll
            for (int q = 0; q < 4; q++) {
                float4 w = w4[q];
                acc[q * 4 + 0] += s * w.x;
                acc[q * 4 + 1] += s * w.y;
                acc[q * 4 + 2] += s * w.z;
                acc[q * 4 + 3] += s * w.w;
            }
        }
    }

    #pragma unroll
    for (int o = 0; o < NK; o++)
        g_def[((size_t)b * NK + o) * HW + p] = acc[o];
}

// ---------------------------------------------------------------------------
// Output conv 16 -> 48 (3 groups of 16) + pixel shuffle + clip
// blockIdx.z = b*3 + g3
// ---------------------------------------------------------------------------
__global__ __launch_bounds__(256, 2)
void outconv_kernel(const float* __restrict__ out_w,
                    const float* __restrict__ out_b,
                    float* __restrict__ out)
{
    __shared__ float sw[16 * 144];     // [c*9+tap][16]
    __shared__ float sp[SPH * SPW];
    __shared__ float sb[16];

    const int tx = threadIdx.x, ty = threadIdx.y;
    const int tid = ty * 16 + tx;
    const int bz = blockIdx.z;
    const int b = bz / 3, g3 = bz - b * 3;
    const int base = g3 * 16;
    const int bx = blockIdx.x * LTW, by = blockIdx.y * LTH;
    const int x0 = bx + tx * 4, y = by + ty;

    for (int i = tid; i < 16 * 144; i += 256) {
        int lo = i / 144, rest = i - lo * 144;
        sw[rest * 16 + lo] = out_w[(size_t)(base + lo) * 144 + rest];
    }
    if (tid < 16) sb[tid] = out_b[base + tid];
    __syncthreads();

    float acc[16][4];
    #pragma unroll
    for (int lo = 0; lo < 16; lo++) {
        float bv = sb[lo];
        #pragma unroll
        for (int px = 0; px < 4; px++) acc[lo][px] = bv;
    }

    for (int c = 0; c < NK; c++) {
        const float* src = g_def + ((size_t)b * NK + c) * HW;
        for (int i = tid; i < SPH * SPW; i += 256) {
            int pr = i / SPW, pc = i - pr * SPW;
            int gy = by - 1 + pr, gx = bx - 1 + pc;
            sp[i] = (gy >= 0 && gy < Hh && gx >= 0 && gx < Ww) ? src[gy * Ww + gx] : 0.f;
        }
        __syncthreads();
        const float* wc = sw + c * 144;
        #pragma unroll
        for (int tr = 0; tr < 3; tr++) {
            float v[6];
            const float* rowp = sp + (ty + tr) * SPW + tx * 4;
            #pragma unroll
            for (int j = 0; j < 6; j++) v[j] = rowp[j];
            #pragma unroll
            for (int tc = 0; tc < 3; tc++) {
                const float4* w4 = (const float4*)(wc + (tr * 3 + tc) * 16);
                #pragma unroll
                for (int q = 0; q < 4; q++) {
                    float4 w = w4[q];
                    #pragma unroll
                    for (int px = 0; px < 4; px++) {
                        float pv = v[tc + px];
                        acc[q * 4 + 0][px] += pv * w.x;
                        acc[q * 4 + 1][px] += pv * w.y;
                        acc[q * 4 + 2][px] += pv * w.z;
                        acc[q * 4 + 3][px] += pv * w.w;
                    }
                }
            }
        }
        __syncthreads();
    }

    if (y < Hh) {
        #pragma unroll
        for (int lo = 0; lo < 16; lo++) {
            int oc = base + lo;
            int cch = oc >> 4, rem = oc & 15;
            int r1 = rem >> 2, r2 = rem & 3;
            #pragma unroll
            for (int px = 0; px < 4; px++) {
                float val = fminf(fmaxf(acc[lo][px], 0.f), 255.f);
                size_t oi = (((size_t)b * NC + cch) * (Hh * SCALE) + (y * SCALE + r1))
                            * (size_t)(Ww * SCALE) + ((x0 + px) * SCALE + r2);
                out[oi] = val;
            }
        }
    }
}

// ---------------------------------------------------------------------------
extern "C" void kernel_launch(void* const* d_in, const int* in_sizes, int n_in,
                              void* d_out, int out_size)
{
    const float* X      = (const float*)d_in[0];
    const float* lstm_w = (const float*)d_in[1];
    const float* lstm_b = (const float*)d_in[2];
    const float* W_ci   = (const float*)d_in[3];
    const float* W_cf   = (const float*)d_in[4];
    const float* W_co   = (const float*)d_in[5];
    const float* off_w  = (const float*)d_in[6];
    const float* off_b  = (const float*)d_in[7];
    const float* mod_w  = (const float*)d_in[8];
    const float* mod_b  = (const float*)d_in[9];
    const float* def_w  = (const float*)d_in[10];
    const float* def_b  = (const float*)d_in[11];
    const float* out_w  = (const float*)d_in[12];
    const float* out_b  = (const float*)d_in[13];
    float* out = (float*)d_out;

    dim3 blk16(16, 16);
    dim3 grid_lstm(Ww / LTW, (Hh + LTH - 1) / LTH, Bn * 4);
    dim3 grid_om(Ww / LTW, (Hh + LTH - 1) / LTH, Bn * 2);
    dim3 grid_oc(Ww / LTW, (Hh + LTH - 1) / LTH, Bn * 3);

    for (int t = 0; t < Tt; t++)
        lstm_step_kernel<<<grid_lstm, blk16>>>(X, lstm_w, lstm_b, W_ci, W_cf, W_co, t);

    offmask_kernel<<<grid_om, blk16>>>(off_w, off_b, mod_w, mod_b);

    dim3 blk32(32, 8);
    dim3 grid_def(Ww / 32, (Hh + 7) / 8, Bn);
    deform_kernel<<<grid_def, blk32>>>(def_w, def_b);

    outconv_kernel<<<grid_oc, blk16>>>(out_w, out_b, out);
}

// round 3
// speedup vs baseline: 2.1564x; 1.1576x over previous
#include <cuda_runtime.h>
#include <math.h>

#define Bn 2
#define Tt 4
#define NC 3
#define NK 16
#define Hh 180
#define Ww 320
#define HW (Hh*Ww)
#define CIN_D (Tt*NK)   // 64
#define OUT_C 48
#define SCALE 4

#define LTW 64          // tile width (pixels)
#define LTH 16          // tile height
#define SPW 68          // staged patch stride (66 used, padded to 68 for 16B alignment)
#define SPH 18
#define SPA (SPH*SPW)   // 1224 floats per channel patch

// Scratch (no cudaMalloc allowed)
__device__ float g_hs[Bn*CIN_D*HW];
__device__ float g_c[Bn*NK*HW];
__device__ float g_om[Bn*27*HW];
__device__ float g_def[Bn*NK*HW];

__device__ __forceinline__ float sig_(float v) {
    return __fdividef(1.f, 1.f + __expf(-v));
}
__device__ __forceinline__ float tanh_(float v) {
    float e = __expf(2.f * v);
    return 1.f - __fdividef(2.f, e + 1.f);
}

// stage one channel patch (with halo + zero pad) into smem buffer
__device__ __forceinline__ void stage_patch(float* dst, const float* src,
                                            int bx, int by, int tid)
{
    #pragma unroll
    for (int i = tid; i < SPA; i += 256) {
        int pr = i / SPW, pc = i - pr * SPW;
        float v = 0.f;
        if (pc < 66 && src) {
            int gy = by - 1 + pr, gx = bx - 1 + pc;
            if (gy >= 0 && gy < Hh && gx >= 0 && gx < Ww) v = src[gy * Ww + gx];
        }
        dst[i] = v;
    }
}

// accumulate one channel's 3x3 conv into acc[16][4] from patch buffer
__device__ __forceinline__ void conv_accum(float acc[16][4], const float* patch,
                                           const float* wc, int tx, int ty)
{
    #pragma unroll
    for (int tr = 0; tr < 3; tr++) {
        const float4* rp = (const float4*)(patch + (ty + tr) * SPW + tx * 4);
        float4 a = rp[0], bq = rp[1];
        float v[6] = {a.x, a.y, a.z, a.w, bq.x, bq.y};
        #pragma unroll
        for (int tc = 0; tc < 3; tc++) {
            const float4* w4 = (const float4*)(wc + (tr * 3 + tc) * 16);
            #pragma unroll
            for (int q = 0; q < 4; q++) {
                float4 w = w4[q];
                #pragma unroll
                for (int px = 0; px < 4; px++) {
                    float pv = v[tc + px];
                    acc[q * 4 + 0][px] += pv * w.x;
                    acc[q * 4 + 1][px] += pv * w.y;
                    acc[q * 4 + 2][px] += pv * w.z;
                    acc[q * 4 + 3][px] += pv * w.w;
                }
            }
        }
    }
}

// ---------------------------------------------------------------------------
// ConvLSTM step. block (16,16); thread = 4 px, 16 outputs (4 k x 4 gates)
// blockIdx.z = b*4 + kg. Double-buffered staging, CH=2 channels per barrier.
// ---------------------------------------------------------------------------
__global__ __launch_bounds__(256, 2)
void lstm_step_kernel(const float* __restrict__ X,
                      const float* __restrict__ lw,
                      const float* __restrict__ lb,
                      const float* __restrict__ Wci,
                      const float* __restrict__ Wcf,
                      const float* __restrict__ Wco,
                      int t)
{
    __shared__ float sw[19 * 9 * 16];
    __shared__ float sp[2][2 * SPA];
    __shared__ float sb[16];

    const int tx = threadIdx.x, ty = threadIdx.y;
    const int tid = ty * 16 + tx;
    const int bz = blockIdx.z;
    const int b = bz >> 2, kg = bz & 3;
    const int bx = blockIdx.x * LTW, by = blockIdx.y * LTH;
    const int x0 = bx + tx * 4, y = by + ty;

    for (int i = tid; i < 19 * 144; i += 256) {
        int lo = i / 171, rest = i - lo * 171;
        int row = (lo >> 2) * NK + kg * 4 + (lo & 3);
        sw[rest * 16 + lo] = lw[row * 171 + rest];
    }
    if (tid < 16)
        sb[tid] = lb[(tid >> 2) * NK + kg * 4 + (tid & 3)];

    const int ncin = (t == 0) ? NC : (NC + NK);
    const int nb = (ncin + 1) >> 1;

    // channel -> source pointer
    #define LSTM_SRC(c) ((c) < NC \
        ? (X + (((size_t)b * Tt + t) * NC + (c)) * HW) \
        : (g_hs + ((size_t)b * CIN_D + (t - 1) * NK + ((c) - NC)) * HW))

    // prologue: stage batch 0
    {
        stage_patch(sp[0], LSTM_SRC(0), bx, by, tid);
        stage_patch(sp[0] + SPA, (1 < ncin) ? LSTM_SRC(1) : (const float*)0, bx, by, tid);
    }
    __syncthreads();

    float acc[16][4];
    #pragma unroll
    for (int lo = 0; lo < 16; lo++) {
        float bv = sb[lo];
        #pragma unroll
        for (int px = 0; px < 4; px++) acc[lo][px] = bv;
    }

    for (int cb = 0; cb < nb; cb++) {
        int cur = cb & 1;
        if (cb + 1 < nb) {
            int cn = (cb + 1) * 2;
            stage_patch(sp[cur ^ 1], LSTM_SRC(cn), bx, by, tid);
            stage_patch(sp[cur ^ 1] + SPA,
                        (cn + 1 < ncin) ? LSTM_SRC(cn + 1) : (const float*)0, bx, by, tid);
        }
        int c0 = cb * 2;
        conv_accum(acc, sp[cur], sw + c0 * 144, tx, ty);
        if (c0 + 1 < ncin)
            conv_accum(acc, sp[cur] + SPA, sw + (c0 + 1) * 144, tx, ty);
        __syncthreads();
    }
    #undef LSTM_SRC

    if (y < Hh) {
        const int p = y * Ww + x0;
        #pragma unroll
        for (int kk = 0; kk < 4; kk++) {
            int k = kg * 4 + kk;
            float ci4[4], cf4[4], co4[4], cp4[4], cn4[4], h4[4];
            *(float4*)ci4 = *(const float4*)(Wci + k * HW + p);
            *(float4*)cf4 = *(const float4*)(Wcf + k * HW + p);
            *(float4*)co4 = *(const float4*)(Wco + k * HW + p);
            if (t == 0) {
                #pragma unroll
                for (int px = 0; px < 4; px++) cp4[px] = 0.f;
            } else {
                *(float4*)cp4 = *(const float4*)(g_c + ((size_t)b * NK + k) * HW + p);
            }
            #pragma unroll
            for (int px = 0; px < 4; px++) {
                float cprev = cp4[px];
                float i_ = sig_(acc[kk][px]      + ci4[px] * cprev);
                float f_ = sig_(acc[4 + kk][px]  + cf4[px] * cprev);
                float cn = f_ * cprev + i_ * tanh_(acc[8 + kk][px]);
                float o_ = sig_(acc[12 + kk][px] + co4[px] * cn);
                cn4[px] = cn;
                h4[px] = o_ * tanh_(cn);
            }
            *(float4*)(g_c + ((size_t)b * NK + k) * HW + p) = *(float4*)cn4;
            *(float4*)(g_hs + ((size_t)b * CIN_D + t * NK + k) * HW + p) = *(float4*)h4;
        }
    }
}

// ---------------------------------------------------------------------------
// Offset+mask conv 64 -> 27. blockIdx.z = b*2 + half. CH=4 double-buffered.
// ---------------------------------------------------------------------------
__global__ __launch_bounds__(256, 2)
void offmask_kernel(const float* __restrict__ off_w,
                    const float* __restrict__ off_b,
                    const float* __restrict__ mod_w,
                    const float* __restrict__ mod_b)
{
    __shared__ float sw[16 * 576];
    __shared__ float sp[2][4 * SPA];
    __shared__ float sb[16];

    const int tx = threadIdx.x, ty = threadIdx.y;
    const int tid = ty * 16 + tx;
    const int bz = blockIdx.z;
    const int b = bz >> 1, half = bz & 1;
    const int base = half * 16;
    const int count = half ? 11 : 16;
    const int bx = blockIdx.x * LTW, by = blockIdx.y * LTH;
    const int x0 = bx + tx * 4, y = by + ty;

    for (int i = tid; i < 16 * 576; i += 256) {
        int lo = i / 576, rest = i - lo * 576;
        int oc = base + lo;
        float v = 0.f;
        if (oc < 18) v = off_w[(size_t)oc * 576 + rest];
        else if (oc < 27) v = mod_w[(size_t)(oc - 18) * 576 + rest];
        sw[rest * 16 + lo] = v;
    }
    if (tid < 16) {
        int oc = base + tid;
        sb[tid] = (oc < 18) ? off_b[oc] : (oc < 27 ? mod_b[oc - 18] : 0.f);
    }

    const float* xb = g_hs + (size_t)b * CIN_D * HW;

    // prologue
    #pragma unroll
    for (int cc = 0; cc < 4; cc++)
        stage_patch(sp[0] + cc * SPA, xb + (size_t)cc * HW, bx, by, tid);
    __syncthreads();

    float acc[16][4];
    #pragma unroll
    for (int lo = 0; lo < 16; lo++) {
        float bv = sb[lo];
        #pragma unroll
        for (int px = 0; px < 4; px++) acc[lo][px] = bv;
    }

    for (int cb = 0; cb < 16; cb++) {
        int cur = cb & 1;
        if (cb + 1 < 16) {
            int cn = (cb + 1) * 4;
            #pragma unroll
            for (int cc = 0; cc < 4; cc++)
                stage_patch(sp[cur ^ 1] + cc * SPA, xb + (size_t)(cn + cc) * HW, bx, by, tid);
        }
        int c0 = cb * 4;
        #pragma unroll
        for (int cc = 0; cc < 4; cc++)
            conv_accum(acc, sp[cur] + cc * SPA, sw + (c0 + cc) * 144, tx, ty);
        __syncthreads();
    }

    if (y < Hh) {
        const int p = y * Ww + x0;
        #pragma unroll
        for (int lo = 0; lo < 16; lo++) {
            if (lo >= count) break;
            int oc = base + lo;
            float o4[4];
            if (oc >= 18) {
                #pragma unroll
                for (int px = 0; px < 4; px++) o4[px] = 2.f * sig_(acc[lo][px]);
            } else {
                #pragma unroll
                for (int px = 0; px < 4; px++) o4[px] = acc[lo][px];
            }
            *(float4*)(g_om + ((size_t)b * 27 + oc) * HW + p) = *(float4*)o4;
        }
    }
}

// ---------------------------------------------------------------------------
// Modulated deformable conv. block (32,8), 1 px/thread, 16 outputs.
// ---------------------------------------------------------------------------
__global__ __launch_bounds__(256)
void deform_kernel(const float* __restrict__ def_w,
                   const float* __restrict__ def_b)
{
    __shared__ float swd[NK * CIN_D * 9];
    __shared__ float sb[NK];

    const int bx = blockIdx.x * 32, by = blockIdx.y * 8;
    const int b = blockIdx.z;
    const int tx = threadIdx.x, ty = threadIdx.y;
    const int tid = ty * 32 + tx;

    for (int i = tid; i < NK * CIN_D * 9; i += 256) {
        int o = i / 576, rest = i - o * 576;
        swd[rest * 16 + o] = def_w[i];
    }
    if (tid < NK) sb[tid] = def_b[tid];
    __syncthreads();

    const int x = bx + tx, y = by + ty;
    if (y >= Hh) return;
    const int p = y * Ww + x;

    const float* xb = g_hs + (size_t)b * CIN_D * HW;
    const float* om = g_om + (size_t)b * 27 * HW;

    float acc[NK];
    #pragma unroll
    for (int o = 0; o < NK; o++) acc[o] = sb[o];

    #pragma unroll
    for (int j = 0; j < 9; j++) {
        int ky = j / 3, kx = j - ky * 3;
        float dy = om[(2 * j) * HW + p];
        float dx = om[(2 * j + 1) * HW + p];
        float m  = om[(18 + j) * HW + p];
        float py = (float)(y - 1 + ky) + dy;
        float px_ = (float)(x - 1 + kx) + dx;
        float y0f = floorf(py), x0f = floorf(px_);
        float wy = py - y0f, wx = px_ - x0f;
        int y0 = (int)y0f, x0 = (int)x0f;
        int y1 = y0 + 1,   x1 = x0 + 1;
        float vy0 = (y0 >= 0 && y0 < Hh) ? 1.f : 0.f;
        float vy1 = (y1 >= 0 && y1 < Hh) ? 1.f : 0.f;
        float vx0 = (x0 >= 0 && x0 < Ww) ? 1.f : 0.f;
        float vx1 = (x1 >= 0 && x1 < Ww) ? 1.f : 0.f;
        int y0c = min(max(y0, 0), Hh - 1), y1c = min(max(y1, 0), Hh - 1);
        int x0c = min(max(x0, 0), Ww - 1), x1c = min(max(x1, 0), Ww - 1);
        float w00 = (1.f - wy) * (1.f - wx) * vy0 * vx0 * m;
        float w01 = (1.f - wy) * wx         * vy0 * vx1 * m;
        float w10 = wy * (1.f - wx)         * vy1 * vx0 * m;
        float w11 = wy * wx                 * vy1 * vx1 * m;
        int o00 = y0c * Ww + x0c, o01 = y0c * Ww + x1c;
        int o10 = y1c * Ww + x0c, o11 = y1c * Ww + x1c;

        #pragma unroll 4
        for (int c = 0; c < CIN_D; c++) {
            const float* pc_ = xb + (size_t)c * HW;
            float s = w00 * pc_[o00] + w01 * pc_[o01]
                    + w10 * pc_[o10] + w11 * pc_[o11];
            const float4* w4 = (const float4*)(swd + (c * 9 + j) * 16);
            #pragma unroll
            for (int q = 0; q < 4; q++) {
                float4 w = w4[q];
                acc[q * 4 + 0] += s * w.x;
                acc[q * 4 + 1] += s * w.y;
                acc[q * 4 + 2] += s * w.z;
                acc[q * 4 + 3] += s * w.w;
            }
        }
    }

    #pragma unroll
    for (int o = 0; o < NK; o++)
        g_def[((size_t)b * NK + o) * HW + p] = acc[o];
}

// ---------------------------------------------------------------------------
// Output conv 16 -> 48 (3 groups of 16) + pixel shuffle + clip. CH=4 double-buf
// ---------------------------------------------------------------------------
__global__ __launch_bounds__(256, 2)
void outconv_kernel(const float* __restrict__ out_w,
                    const float* __restrict__ out_b,
                    float* __restrict__ out)
{
    __shared__ float sw[16 * 144];
    __shared__ float sp[2][4 * SPA];
    __shared__ float sb[16];

    const int tx = threadIdx.x, ty = threadIdx.y;
    const int tid = ty * 16 + tx;
    const int bz = blockIdx.z;
    const int b = bz / 3, g3 = bz - b * 3;
    const int base = g3 * 16;
    const int bx = blockIdx.x * LTW, by = blockIdx.y * LTH;
    const int x0 = bx + tx * 4, y = by + ty;

    for (int i = tid; i < 16 * 144; i += 256) {
        int lo = i / 144, rest = i - lo * 144;
        sw[rest * 16 + lo] = out_w[(size_t)(base + lo) * 144 + rest];
    }
    if (tid < 16) sb[tid] = out_b[base + tid];

    const float* xb = g_def + (size_t)b * NK * HW;

    #pragma unroll
    for (int cc = 0; cc < 4; cc++)
        stage_patch(sp[0] + cc * SPA, xb + (size_t)cc * HW, bx, by, tid);
    __syncthreads();

    float acc[16][4];
    #pragma unroll
    for (int lo = 0; lo < 16; lo++) {
        float bv = sb[lo];
        #pragma unroll
        for (int px = 0; px < 4; px++) acc[lo][px] = bv;
    }

    for (int cb = 0; cb < 4; cb++) {
        int cur = cb & 1;
        if (cb + 1 < 4) {
            int cn = (cb + 1) * 4;
            #pragma unroll
            for (int cc = 0; cc < 4; cc++)
                stage_patch(sp[cur ^ 1] + cc * SPA, xb + (size_t)(cn + cc) * HW, bx, by, tid);
        }
        int c0 = cb * 4;
        #pragma unroll
        for (int cc = 0; cc < 4; cc++)
            conv_accum(acc, sp[cur] + cc * SPA, sw + (c0 + cc) * 144, tx, ty);
        __syncthreads();
    }

    if (y < Hh) {
        #pragma unroll
        for (int lo = 0; lo < 16; lo++) {
            int oc = base + lo;
            int cch = oc >> 4, rem = oc & 15;
            int r1 = rem >> 2, r2 = rem & 3;
            #pragma unroll
            for (int px = 0; px < 4; px++) {
                float val = fminf(fmaxf(acc[lo][px], 0.f), 255.f);
                size_t oi = (((size_t)b * NC + cch) * (Hh * SCALE) + (y * SCALE + r1))
                            * (size_t)(Ww * SCALE) + ((x0 + px) * SCALE + r2);
                out[oi] = val;
            }
        }
    }
}

// ---------------------------------------------------------------------------
extern "C" void kernel_launch(void* const* d_in, const int* in_sizes, int n_in,
                              void* d_out, int out_size)
{
    const float* X      = (const float*)d_in[0];
    const float* lstm_w = (const float*)d_in[1];
    const float* lstm_b = (const float*)d_in[2];
    const float* W_ci   = (const float*)d_in[3];
    const float* W_cf   = (const float*)d_in[4];
    const float* W_co   = (const float*)d_in[5];
    const float* off_w  = (const float*)d_in[6];
    const float* off_b  = (const float*)d_in[7];
    const float* mod_w  = (const float*)d_in[8];
    const float* mod_b  = (const float*)d_in[9];
    const float* def_w  = (const float*)d_in[10];
    const float* def_b  = (const float*)d_in[11];
    const float* out_w  = (const float*)d_in[12];
    const float* out_b  = (const float*)d_in[13];
    float* out = (float*)d_out;

    dim3 blk16(16, 16);
    dim3 grid_lstm(Ww / LTW, (Hh + LTH - 1) / LTH, Bn * 4);
    dim3 grid_om(Ww / LTW, (Hh + LTH - 1) / LTH, Bn * 2);
    dim3 grid_oc(Ww / LTW, (Hh + LTH - 1) / LTH, Bn * 3);

    for (int t = 0; t < Tt; t++)
        lstm_step_kernel<<<grid_lstm, blk16>>>(X, lstm_w, lstm_b, W_ci, W_cf, W_co, t);

    offmask_kernel<<<grid_om, blk16>>>(off_w, off_b, mod_w, mod_b);

    dim3 blk32(32, 8);
    dim3 grid_def(Ww / 32, (Hh + 7) / 8, Bn);
    deform_kernel<<<grid_def, blk32>>>(def_w, def_b);

    outconv_kernel<<<grid_oc, blk16>>>(out_w, out_b, out);
}

// round 5
// speedup vs baseline: 2.6772x; 1.2415x over previous
#include <cuda_runtime.h>
#include <math.h>

#define Bn 2
#define Tt 4
#define NC 3
#define NK 16
#define Hh 180
#define Ww 320
#define HW (Hh*Ww)
#define CIN_D (Tt*NK)   // 64
#define OUT_C 48
#define SCALE 4

#define LTW 64
#define LTH 16
#define SPW 68          // padded patch stride
#define SPH 18
#define SPA (SPH*SPW)   // 1224 floats

// Scratch (no cudaMalloc allowed)
__device__ float g_hs[Bn*CIN_D*HW];
__device__ float g_c[Bn*NK*HW];
__device__ float g_om[Bn*27*HW];
__device__ float g_def[Bn*NK*HW];

__device__ __forceinline__ float sig_(float v) {
    return __fdividef(1.f, 1.f + __expf(-v));
}
__device__ __forceinline__ float tanh_(float v) {
    float e = __expf(2.f * v);
    return 1.f - __fdividef(2.f, e + 1.f);
}

__device__ __forceinline__ void cp_async4(float* dst_smem, const float* src) {
    unsigned d = (unsigned)__cvta_generic_to_shared(dst_smem);
    asm volatile("cp.async.ca.shared.global [%0], [%1], 4;" :: "r"(d), "l"(src));
}
#define CP_COMMIT() asm volatile("cp.async.commit_group;" ::: "memory")
#define CP_WAIT0()  asm volatile("cp.async.wait_group 0;" ::: "memory")

// async-stage one channel patch (halo + zero pad)
__device__ __forceinline__ void stage_patch_async(float* dst, const float* src,
                                                  int bx, int by, int tid)
{
    #pragma unroll
    for (int i = tid; i < SPA; i += 256) {
        int pr = i / SPW, pc = i - pr * SPW;
        int gy = by - 1 + pr, gx = bx - 1 + pc;
        if (pc < 66 && gy >= 0 && gy < Hh && gx >= 0 && gx < Ww)
            cp_async4(dst + i, src + gy * Ww + gx);
        else
            dst[i] = 0.f;
    }
}

// accumulate one channel's 3x3 conv into acc[16][4]
__device__ __forceinline__ void conv_accum(float acc[16][4], const float* patch,
                                           const float* wc, int tx, int ty)
{
    #pragma unroll
    for (int tr = 0; tr < 3; tr++) {
        const float4* rp = (const float4*)(patch + (ty + tr) * SPW + tx * 4);
        float4 a = rp[0], bq = rp[1];
        float v[6] = {a.x, a.y, a.z, a.w, bq.x, bq.y};
        #pragma unroll
        for (int tc = 0; tc < 3; tc++) {
            const float4* w4 = (const float4*)(wc + (tr * 3 + tc) * 16);
            #pragma unroll
            for (int q = 0; q < 4; q++) {
                float4 w = w4[q];
                #pragma unroll
                for (int px = 0; px < 4; px++) {
                    float pv = v[tc + px];
                    acc[q * 4 + 0][px] += pv * w.x;
                    acc[q * 4 + 1][px] += pv * w.y;
                    acc[q * 4 + 2][px] += pv * w.z;
                    acc[q * 4 + 3][px] += pv * w.w;
                }
            }
        }
    }
}

// ---------------------------------------------------------------------------
// ConvLSTM step. block (16,16); thread = 4 px, 16 outputs (4 k x 4 gates)
// blockIdx.z = b*4 + kg. cp.async pipelined, CH=4 channels per batch.
// ---------------------------------------------------------------------------
__global__ __launch_bounds__(256, 2)
void lstm_step_kernel(const float* __restrict__ X,
                      const float* __restrict__ lw,
                      const float* __restrict__ lb,
                      const float* __restrict__ Wci,
                      const float* __restrict__ Wcf,
                      const float* __restrict__ Wco,
                      int t)
{
    __shared__ float sw[19 * 9 * 16];
    __shared__ float sp[2][4 * SPA];
    __shared__ float sb[16];

    const int tx = threadIdx.x, ty = threadIdx.y;
    const int tid = ty * 16 + tx;
    const int bz = blockIdx.z;
    const int b = bz >> 2, kg = bz & 3;
    const int bx = blockIdx.x * LTW, by = blockIdx.y * LTH;
    const int x0 = bx + tx * 4, y = by + ty;

    for (int i = tid; i < 19 * 144; i += 256) {
        int lo = i / 171, rest = i - lo * 171;
        int row = (lo >> 2) * NK + kg * 4 + (lo & 3);
        sw[rest * 16 + lo] = lw[row * 171 + rest];
    }
    if (tid < 16)
        sb[tid] = lb[(tid >> 2) * NK + kg * 4 + (tid & 3)];

    const int ncin = (t == 0) ? NC : (NC + NK);
    const int nb = (ncin + 3) >> 2;

    #define LSTM_SRC(c) ((c) < NC \
        ? (X + (((size_t)b * Tt + t) * NC + (c)) * HW) \
        : (g_hs + ((size_t)b * CIN_D + (t - 1) * NK + ((c) - NC)) * HW))

    // prologue: batch 0
    #pragma unroll
    for (int cc = 0; cc < 4; cc++)
        if (cc < ncin) stage_patch_async(sp[0] + cc * SPA, LSTM_SRC(cc), bx, by, tid);
    CP_COMMIT();

    // make sb/sw visible to all threads before acc-init / compute
    __syncthreads();

    float acc[16][4];
    #pragma unroll
    for (int lo = 0; lo < 16; lo++) {
        float bv = sb[lo];
        #pragma unroll
        for (int px = 0; px < 4; px++) acc[lo][px] = bv;
    }

    for (int cb = 0; cb < nb; cb++) {
        int cur = cb & 1;
        CP_WAIT0();
        __syncthreads();
        if (cb + 1 < nb) {
            int cn = (cb + 1) * 4;
            #pragma unroll
            for (int cc = 0; cc < 4; cc++)
                if (cn + cc < ncin)
                    stage_patch_async(sp[cur ^ 1] + cc * SPA, LSTM_SRC(cn + cc), bx, by, tid);
        }
        CP_COMMIT();
        int c0 = cb * 4;
        #pragma unroll
        for (int cc = 0; cc < 4; cc++)
            if (c0 + cc < ncin)
                conv_accum(acc, sp[cur] + cc * SPA, sw + (c0 + cc) * 144, tx, ty);
    }
    #undef LSTM_SRC

    if (y < Hh) {
        const int p = y * Ww + x0;
        #pragma unroll
        for (int kk = 0; kk < 4; kk++) {
            int k = kg * 4 + kk;
            float ci4[4], cf4[4], co4[4], cp4[4], cn4[4], h4[4];
            *(float4*)ci4 = *(const float4*)(Wci + k * HW + p);
            *(float4*)cf4 = *(const float4*)(Wcf + k * HW + p);
            *(float4*)co4 = *(const float4*)(Wco + k * HW + p);
            if (t == 0) {
                #pragma unroll
                for (int px = 0; px < 4; px++) cp4[px] = 0.f;
            } else {
                *(float4*)cp4 = *(const float4*)(g_c + ((size_t)b * NK + k) * HW + p);
            }
            #pragma unroll
            for (int px = 0; px < 4; px++) {
                float cprev = cp4[px];
                float i_ = sig_(acc[kk][px]      + ci4[px] * cprev);
                float f_ = sig_(acc[4 + kk][px]  + cf4[px] * cprev);
                float cn = f_ * cprev + i_ * tanh_(acc[8 + kk][px]);
                float o_ = sig_(acc[12 + kk][px] + co4[px] * cn);
                cn4[px] = cn;
                h4[px] = o_ * tanh_(cn);
            }
            *(float4*)(g_c + ((size_t)b * NK + k) * HW + p) = *(float4*)cn4;
            *(float4*)(g_hs + ((size_t)b * CIN_D + t * NK + k) * HW + p) = *(float4*)h4;
        }
    }
}

// ---------------------------------------------------------------------------
// Offset+mask conv 64 -> 27. blockIdx.z = b*2 + half. CH=4 cp.async pipeline.
// ---------------------------------------------------------------------------
__global__ __launch_bounds__(256, 2)
void offmask_kernel(const float* __restrict__ off_w,
                    const float* __restrict__ off_b,
                    const float* __restrict__ mod_w,
                    const float* __restrict__ mod_b)
{
    __shared__ float sw[16 * 576];
    __shared__ float sp[2][4 * SPA];
    __shared__ float sb[16];

    const int tx = threadIdx.x, ty = threadIdx.y;
    const int tid = ty * 16 + tx;
    const int bz = blockIdx.z;
    const int b = bz >> 1, half = bz & 1;
    const int base = half * 16;
    const int count = half ? 11 : 16;
    const int bx = blockIdx.x * LTW, by = blockIdx.y * LTH;
    const int x0 = bx + tx * 4, y = by + ty;

    for (int i = tid; i < 16 * 576; i += 256) {
        int lo = i / 576, rest = i - lo * 576;
        int oc = base + lo;
        float v = 0.f;
        if (oc < 18) v = off_w[(size_t)oc * 576 + rest];
        else if (oc < 27) v = mod_w[(size_t)(oc - 18) * 576 + rest];
        sw[rest * 16 + lo] = v;
    }
    if (tid < 16) {
        int oc = base + tid;
        sb[tid] = (oc < 18) ? off_b[oc] : (oc < 27 ? mod_b[oc - 18] : 0.f);
    }

    const float* xb = g_hs + (size_t)b * CIN_D * HW;

    #pragma unroll
    for (int cc = 0; cc < 4; cc++)
        stage_patch_async(sp[0] + cc * SPA, xb + (size_t)cc * HW, bx, by, tid);
    CP_COMMIT();

    __syncthreads();   // sb/sw visible before acc-init / compute

    float acc[16][4];
    #pragma unroll
    for (int lo = 0; lo < 16; lo++) {
        float bv = sb[lo];
        #pragma unroll
        for (int px = 0; px < 4; px++) acc[lo][px] = bv;
    }

    for (int cb = 0; cb < 16; cb++) {
        int cur = cb & 1;
        CP_WAIT0();
        __syncthreads();
        if (cb + 1 < 16) {
            int cn = (cb + 1) * 4;
            #pragma unroll
            for (int cc = 0; cc < 4; cc++)
                stage_patch_async(sp[cur ^ 1] + cc * SPA, xb + (size_t)(cn + cc) * HW, bx, by, tid);
        }
        CP_COMMIT();
        int c0 = cb * 4;
        #pragma unroll
        for (int cc = 0; cc < 4; cc++)
            conv_accum(acc, sp[cur] + cc * SPA, sw + (c0 + cc) * 144, tx, ty);
    }

    if (y < Hh) {
        const int p = y * Ww + x0;
        #pragma unroll
        for (int lo = 0; lo < 16; lo++) {
            if (lo >= count) break;
            int oc = base + lo;
            float o4[4];
            if (oc >= 18) {
                #pragma unroll
                for (int px = 0; px < 4; px++) o4[px] = 2.f * sig_(acc[lo][px]);
            } else {
                #pragma unroll
                for (int px = 0; px < 4; px++) o4[px] = acc[lo][px];
            }
            *(float4*)(g_om + ((size_t)b * 27 + oc) * HW + p) = *(float4*)o4;
        }
    }
}

// ---------------------------------------------------------------------------
// Modulated deformable conv. block (32,8), 1 px/thread, 16 outputs.
// ---------------------------------------------------------------------------
__global__ __launch_bounds__(256)
void deform_kernel(const float* __restrict__ def_w,
                   const float* __restrict__ def_b)
{
    __shared__ float swd[NK * CIN_D * 9];
    __shared__ float sb[NK];

    const int bx = blockIdx.x * 32, by = blockIdx.y * 8;
    const int b = blockIdx.z;
    const int tx = threadIdx.x, ty = threadIdx.y;
    const int tid = ty * 32 + tx;

    for (int i = tid; i < NK * CIN_D * 9; i += 256) {
        int o = i / 576, rest = i - o * 576;
        swd[rest * 16 + o] = def_w[i];
    }
    if (tid < NK) sb[tid] = def_b[tid];
    __syncthreads();

    const int x = bx + tx, y = by + ty;
    if (y >= Hh) return;
    const int p = y * Ww + x;

    const float* xb = g_hs + (size_t)b * CIN_D * HW;
    const float* om = g_om + (size_t)b * 27 * HW;

    float acc[NK];
    #pragma unroll
    for (int o = 0; o < NK; o++) acc[o] = sb[o];

    #pragma unroll
    for (int j = 0; j < 9; j++) {
        int ky = j / 3, kx = j - ky * 3;
        float dy = om[(2 * j) * HW + p];
        float dx = om[(2 * j + 1) * HW + p];
        float m  = om[(18 + j) * HW + p];
        float py = (float)(y - 1 + ky) + dy;
        float px_ = (float)(x - 1 + kx) + dx;
        float y0f = floorf(py), x0f = floorf(px_);
        float wy = py - y0f, wx = px_ - x0f;
        int y0 = (int)y0f, x0 = (int)x0f;
        int y1 = y0 + 1,   x1 = x0 + 1;
        float vy0 = (y0 >= 0 && y0 < Hh) ? 1.f : 0.f;
        float vy1 = (y1 >= 0 && y1 < Hh) ? 1.f : 0.f;
        float vx0 = (x0 >= 0 && x0 < Ww) ? 1.f : 0.f;
        float vx1 = (x1 >= 0 && x1 < Ww) ? 1.f : 0.f;
        int y0c = min(max(y0, 0), Hh - 1), y1c = min(max(y1, 0), Hh - 1);
        int x0c = min(max(x0, 0), Ww - 1), x1c = min(max(x1, 0), Ww - 1);
        float w00 = (1.f - wy) * (1.f - wx) * vy0 * vx0 * m;
        float w01 = (1.f - wy) * wx         * vy0 * vx1 * m;
        float w10 = wy * (1.f - wx)         * vy1 * vx0 * m;
        float w11 = wy * wx                 * vy1 * vx1 * m;
        int o00 = y0c * Ww + x0c, o01 = y0c * Ww + x1c;
        int o10 = y1c * Ww + x0c, o11 = y1c * Ww + x1c;

        #pragma unroll 4
        for (int c = 0; c < CIN_D; c++) {
            const float* pc_ = xb + (size_t)c * HW;
            float s = w00 * pc_[o00] + w01 * pc_[o01]
                    + w10 * pc_[o10] + w11 * pc_[o11];
            const float4* w4 = (const float4*)(swd + (c * 9 + j) * 16);
            #pragma unroll
            for (int q = 0; q < 4; q++) {
                float4 w = w4[q];
                acc[q * 4 + 0] += s * w.x;
                acc[q * 4 + 1] += s * w.y;
                acc[q * 4 + 2] += s * w.z;
                acc[q * 4 + 3] += s * w.w;
            }
        }
    }

    #pragma unroll
    for (int o = 0; o < NK; o++)
        g_def[((size_t)b * NK + o) * HW + p] = acc[o];
}

// ---------------------------------------------------------------------------
// Output conv 16 -> 48 (3 groups of 16) + pixel shuffle + clip. cp.async CH=4.
// ---------------------------------------------------------------------------
__global__ __launch_bounds__(256, 2)
void outconv_kernel(const float* __restrict__ out_w,
                    const float* __restrict__ out_b,
                    float* __restrict__ out)
{
    __shared__ float sw[16 * 144];
    __shared__ float sp[2][4 * SPA];
    __shared__ float sb[16];

    const int tx = threadIdx.x, ty = threadIdx.y;
    const int tid = ty * 16 + tx;
    const int bz = blockIdx.z;
    const int b = bz / 3, g3 = bz - b * 3;
    const int base = g3 * 16;
    const int bx = blockIdx.x * LTW, by = blockIdx.y * LTH;
    const int x0 = bx + tx * 4, y = by + ty;

    for (int i = tid; i < 16 * 144; i += 256) {
        int lo = i / 144, rest = i - lo * 144;
        sw[rest * 16 + lo] = out_w[(size_t)(base + lo) * 144 + rest];
    }
    if (tid < 16) sb[tid] = out_b[base + tid];

    const float* xb = g_def + (size_t)b * NK * HW;

    #pragma unroll
    for (int cc = 0; cc < 4; cc++)
        stage_patch_async(sp[0] + cc * SPA, xb + (size_t)cc * HW, bx, by, tid);
    CP_COMMIT();

    __syncthreads();   // sb/sw visible before acc-init / compute

    float acc[16][4];
    #pragma unroll
    for (int lo = 0; lo < 16; lo++) {
        float bv = sb[lo];
        #pragma unroll
        for (int px = 0; px < 4; px++) acc[lo][px] = bv;
    }

    for (int cb = 0; cb < 4; cb++) {
        int cur = cb & 1;
        CP_WAIT0();
        __syncthreads();
        if (cb + 1 < 4) {
            int cn = (cb + 1) * 4;
            #pragma unroll
            for (int cc = 0; cc < 4; cc++)
                stage_patch_async(sp[cur ^ 1] + cc * SPA, xb + (size_t)(cn + cc) * HW, bx, by, tid);
        }
        CP_COMMIT();
        int c0 = cb * 4;
        #pragma unroll
        for (int cc = 0; cc < 4; cc++)
            conv_accum(acc, sp[cur] + cc * SPA, sw + (c0 + cc) * 144, tx, ty);
    }

    if (y < Hh) {
        #pragma unroll
        for (int lo = 0; lo < 16; lo++) {
            int oc = base + lo;
            int cch = oc >> 4, rem = oc & 15;
            int r1 = rem >> 2, r2 = rem & 3;
            #pragma unroll
            for (int px = 0; px < 4; px++) {
                float val = fminf(fmaxf(acc[lo][px], 0.f), 255.f);
                size_t oi = (((size_t)b * NC + cch) * (Hh * SCALE) + (y * SCALE + r1))
                            * (size_t)(Ww * SCALE) + ((x0 + px) * SCALE + r2);
                out[oi] = val;
            }
        }
    }
}

// ---------------------------------------------------------------------------
extern "C" void kernel_launch(void* const* d_in, const int* in_sizes, int n_in,
                              void* d_out, int out_size)
{
    const float* X      = (const float*)d_in[0];
    const float* lstm_w = (const float*)d_in[1];
    const float* lstm_b = (const float*)d_in[2];
    const float* W_ci   = (const float*)d_in[3];
    const float* W_cf   = (const float*)d_in[4];
    const float* W_co   = (const float*)d_in[5];
    const float* off_w  = (const float*)d_in[6];
    const float* off_b  = (const float*)d_in[7];
    const float* mod_w  = (const float*)d_in[8];
    const float* mod_b  = (const float*)d_in[9];
    const float* def_w  = (const float*)d_in[10];
    const float* def_b  = (const float*)d_in[11];
    const float* out_w  = (const float*)d_in[12];
    const float* out_b  = (const float*)d_in[13];
    float* out = (float*)d_out;

    dim3 blk16(16, 16);
    dim3 grid_lstm(Ww / LTW, (Hh + LTH - 1) / LTH, Bn * 4);
    dim3 grid_om(Ww / LTW, (Hh + LTH - 1) / LTH, Bn * 2);
    dim3 grid_oc(Ww / LTW, (Hh + LTH - 1) / LTH, Bn * 3);

    for (int t = 0; t < Tt; t++)
        lstm_step_kernel<<<grid_lstm, blk16>>>(X, lstm_w, lstm_b, W_ci, W_cf, W_co, t);

    offmask_kernel<<<grid_om, blk16>>>(off_w, off_b, mod_w, mod_b);

    dim3 blk32(32, 8);
    dim3 grid_def(Ww / 32, (Hh + 7) / 8, Bn);
    deform_kernel<<<grid_def, blk32>>>(def_w, def_b);

    outconv_kernel<<<grid_oc, blk16>>>(out_w, out_b, out);
}